// round 16
// baseline (speedup 1.0000x reference)
#include <cuda_runtime.h>
#include <cstdint>
#include <cstddef>

// Problem constants
#define BB 4096
#define TT 128
#define FF 128
#define AA 384
#define G4 512            // 4*F gate width
#define BT (BB*TT)        // 524288

// ---------------- device scratch (static: allocated at module load, allowed) ----
__device__ float g_Z[(size_t)BT * G4];      // 1 GiB: precomputed input projections
__device__ float g_Hn[(size_t)BB * FF];     // final hidden states
__device__ float g_Wic[AA * G4];            // tf32-rounded Wi
__device__ float g_Whc[FF * G4];            // tf32-rounded Wh

// ---------------- helpers ----------------
__device__ __forceinline__ unsigned tf32r(float x) {
    unsigned r;
    asm("cvt.rna.tf32.f32 %0, %1;" : "=r"(r) : "f"(x));
    return r;
}

__device__ __forceinline__ void mma_tf32(float (&c)[4],
                                         unsigned a0, unsigned a1, unsigned a2, unsigned a3,
                                         unsigned b0, unsigned b1) {
    asm volatile(
        "mma.sync.aligned.m16n8k8.row.col.f32.tf32.tf32.f32 "
        "{%0,%1,%2,%3},{%4,%5,%6,%7},{%8,%9},{%0,%1,%2,%3};"
        : "+f"(c[0]), "+f"(c[1]), "+f"(c[2]), "+f"(c[3])
        : "r"(a0), "r"(a1), "r"(a2), "r"(a3), "r"(b0), "r"(b1));
}

__device__ __forceinline__ float sigm(float x)   { return 1.0f / (1.0f + __expf(-x)); }
__device__ __forceinline__ float tanh_f(float x) { return 1.0f - 2.0f / (__expf(2.0f * x) + 1.0f); }

// ---------------- kernel 0: round weights to tf32 once per launch ----------------
__global__ void cvt_weights(const float* __restrict__ Wi, const float* __restrict__ Wh) {
    int i = blockIdx.x * 256 + threadIdx.x;
    if (i < AA * G4) g_Wic[i] = __uint_as_float(tf32r(Wi[i]));
    if (i < FF * G4) g_Whc[i] = __uint_as_float(tf32r(Wh[i]));
}

// ---------------- kernel 1: Z = [seq|seq_e|seq_t] @ Wi  (tf32 mma GEMM) -----------
// Block tile 128(M) x 128(N), K-blocks of 32.  8 warps: 4(M) x 2(N), warp tile 32x64.
__global__ __launch_bounds__(256) void phase1_gemm(
    const float* __restrict__ seq, const float* __restrict__ seq_e,
    const float* __restrict__ seq_t)
{
    __shared__ float As[128 * 36];   // [m][k] padded
    __shared__ float Bs[32 * 132];   // [k][n] padded

    const int tid = threadIdx.x;
    const int warp = tid >> 5, lane = tid & 31;
    const int gq = lane >> 2, t4 = lane & 3;      // groupID, threadID_in_group
    const int warp_m = warp & 3, warp_n = warp >> 2;
    const int bm = blockIdx.x, bn = blockIdx.y;

    float acc[2][8][4];
#pragma unroll
    for (int im = 0; im < 2; im++)
#pragma unroll
        for (int jn = 0; jn < 8; jn++)
#pragma unroll
            for (int q = 0; q < 4; q++) acc[im][jn][q] = 0.f;

    float4 ar[4], br[4];

    // prologue global load (k-block 0)
    {
        const float* Xp = seq;      // k0=0 -> segment 0
#pragma unroll
        for (int i = 0; i < 4; i++) {
            int q = i * 256 + tid;
            int row = q >> 3, c4 = q & 7;
            ar[i] = *(const float4*)&Xp[(size_t)(bm * 128 + row) * 128 + c4 * 4];
            int kr = q >> 5, c4b = q & 31;
            br[i] = *(const float4*)&g_Wic[(size_t)kr * G4 + bn * 128 + c4b * 4];
        }
    }

    for (int kb = 0; kb < 12; kb++) {
        // store staged tile to smem (convert A to tf32)
#pragma unroll
        for (int i = 0; i < 4; i++) {
            int q = i * 256 + tid;
            int row = q >> 3, c4 = q & 7;
            float4 v = ar[i], cv;
            cv.x = __uint_as_float(tf32r(v.x));
            cv.y = __uint_as_float(tf32r(v.y));
            cv.z = __uint_as_float(tf32r(v.z));
            cv.w = __uint_as_float(tf32r(v.w));
            *(float4*)&As[row * 36 + c4 * 4] = cv;
            int kr = q >> 5, c4b = q & 31;
            *(float4*)&Bs[kr * 132 + c4b * 4] = br[i];
        }
        __syncthreads();

        // prefetch next k-block into registers
        if (kb < 11) {
            int k0 = (kb + 1) * 32;
            int seg = k0 >> 7, off = k0 & 127;
            const float* Xp = (seg == 0) ? seq : ((seg == 1) ? seq_e : seq_t);
#pragma unroll
            for (int i = 0; i < 4; i++) {
                int q = i * 256 + tid;
                int row = q >> 3, c4 = q & 7;
                ar[i] = *(const float4*)&Xp[(size_t)(bm * 128 + row) * 128 + off + c4 * 4];
                int kr = q >> 5, c4b = q & 31;
                br[i] = *(const float4*)&g_Wic[(size_t)(k0 + kr) * G4 + bn * 128 + c4b * 4];
            }
        }

        // compute 4 k8 steps from smem
#pragma unroll
        for (int kk = 0; kk < 4; kk++) {
            int ks = kk * 8;
            unsigned a[2][4], b[8][2];
#pragma unroll
            for (int im = 0; im < 2; im++) {
                int mr = warp_m * 32 + im * 16;
                a[im][0] = __float_as_uint(As[(mr + gq) * 36 + ks + t4]);
                a[im][1] = __float_as_uint(As[(mr + gq + 8) * 36 + ks + t4]);
                a[im][2] = __float_as_uint(As[(mr + gq) * 36 + ks + t4 + 4]);
                a[im][3] = __float_as_uint(As[(mr + gq + 8) * 36 + ks + t4 + 4]);
            }
#pragma unroll
            for (int jn = 0; jn < 8; jn++) {
                int nc = warp_n * 64 + jn * 8 + gq;
                b[jn][0] = __float_as_uint(Bs[(ks + t4) * 132 + nc]);
                b[jn][1] = __float_as_uint(Bs[(ks + t4 + 4) * 132 + nc]);
            }
#pragma unroll
            for (int im = 0; im < 2; im++)
#pragma unroll
                for (int jn = 0; jn < 8; jn++)
                    mma_tf32(acc[im][jn], a[im][0], a[im][1], a[im][2], a[im][3],
                             b[jn][0], b[jn][1]);
        }
        __syncthreads();
    }

    // epilogue: store Z
#pragma unroll
    for (int im = 0; im < 2; im++)
#pragma unroll
        for (int jn = 0; jn < 8; jn++) {
            size_t row = (size_t)bm * 128 + warp_m * 32 + im * 16 + gq;
            int col = bn * 128 + warp_n * 64 + jn * 8 + 2 * t4;
            float2 v01 = make_float2(acc[im][jn][0], acc[im][jn][1]);
            float2 v23 = make_float2(acc[im][jn][2], acc[im][jn][3]);
            *(float2*)&g_Z[row * G4 + col] = v01;
            *(float2*)&g_Z[(row + 8) * G4 + col] = v23;
        }
}

// ---------------- kernel 2: recurrence ----------------
// 128 blocks x 32 rows each. h,c in SMEM; per step G = h @ Wh via tf32 mma with
// Wh fragments streamed from L2; gates in exact fp32.
#define P2_SMEM ((32*132 + 32*128 + 32*516 + 512) * 4)

__global__ __launch_bounds__(256) void phase2_lstm(const float* __restrict__ bh,
                                                   float* __restrict__ Hn)
{
    extern __shared__ float sm[];
    float* h_s  = sm;                  // 32 x 132 (tf32-rounded h)
    float* c_s  = h_s + 32 * 132;      // 32 x 128
    float* g_s  = c_s + 32 * 128;      // 32 x 516 (gate pre-activations, h@Wh part)
    float* bh_s = g_s + 32 * 516;      // 512

    const int tid = threadIdx.x;
    const int warp = tid >> 5, lane = tid & 31;
    const int gq = lane >> 2, t4 = lane & 3;
    const int n0 = warp * 64;
    const int r0 = blockIdx.x * 32;

    for (int i = tid; i < 32 * 132; i += 256) h_s[i] = 0.f;
    for (int i = tid; i < 32 * 128; i += 256) c_s[i] = 0.f;
    for (int i = tid; i < 512; i += 256) bh_s[i] = bh[i];
    __syncthreads();

    for (int t = 0; t < TT; t++) {
        float acc[2][8][4];
#pragma unroll
        for (int im = 0; im < 2; im++)
#pragma unroll
            for (int jn = 0; jn < 8; jn++)
#pragma unroll
                for (int q = 0; q < 4; q++) acc[im][jn][q] = 0.f;

#pragma unroll
        for (int kt = 0; kt < 16; kt++) {
            int ks = kt * 8;
            unsigned a[2][4];
#pragma unroll
            for (int im = 0; im < 2; im++) {
                int mr = im * 16;
                a[im][0] = __float_as_uint(h_s[(mr + gq) * 132 + ks + t4]);
                a[im][1] = __float_as_uint(h_s[(mr + gq + 8) * 132 + ks + t4]);
                a[im][2] = __float_as_uint(h_s[(mr + gq) * 132 + ks + t4 + 4]);
                a[im][3] = __float_as_uint(h_s[(mr + gq + 8) * 132 + ks + t4 + 4]);
            }
#pragma unroll
            for (int jn = 0; jn < 8; jn++) {
                int nc = n0 + jn * 8 + gq;
                unsigned b0 = __float_as_uint(__ldg(&g_Whc[(ks + t4) * G4 + nc]));
                unsigned b1 = __float_as_uint(__ldg(&g_Whc[(ks + t4 + 4) * G4 + nc]));
#pragma unroll
                for (int im = 0; im < 2; im++)
                    mma_tf32(acc[im][jn], a[im][0], a[im][1], a[im][2], a[im][3], b0, b1);
            }
        }

        // write h@Wh gate contributions to smem
#pragma unroll
        for (int im = 0; im < 2; im++)
#pragma unroll
            for (int jn = 0; jn < 8; jn++) {
                int mr = im * 16 + gq;
                int nc = n0 + jn * 8 + 2 * t4;
                *(float2*)&g_s[mr * 516 + nc] =
                    make_float2(acc[im][jn][0], acc[im][jn][1]);
                *(float2*)&g_s[(mr + 8) * 516 + nc] =
                    make_float2(acc[im][jn][2], acc[im][jn][3]);
            }
        __syncthreads();

        // gate nonlinearity + state update (exact fp32)
#pragma unroll 4
        for (int it = 0; it < 16; it++) {
            int idx = it * 256 + tid;
            int r = idx >> 7, j = idx & 127;
            size_t zbase = ((size_t)(r0 + r) * TT + t) * G4;
            float zi = g_Z[zbase + j];
            float zf = g_Z[zbase + 128 + j];
            float zg = g_Z[zbase + 256 + j];
            float zo = g_Z[zbase + 384 + j];
            float gi = g_s[r * 516 + j]       + zi + bh_s[j];
            float gf = g_s[r * 516 + 128 + j] + zf + bh_s[128 + j];
            float gg = g_s[r * 516 + 256 + j] + zg + bh_s[256 + j];
            float go = g_s[r * 516 + 384 + j] + zo + bh_s[384 + j];
            float co = c_s[r * 128 + j];
            float cn = sigm(gf) * co + sigm(gi) * tanh_f(gg);
            float hv = sigm(go) * tanh_f(cn);
            c_s[r * 128 + j] = cn;
            if (t == TT - 1) Hn[(size_t)(r0 + r) * FF + j] = hv;
            h_s[r * 132 + j] = __uint_as_float(tf32r(hv));
        }
        __syncthreads();
    }
}

// ---------------- kernel 3: merge MLP (fp32) ----------------
#define MG_SMEM ((256*128 + 32*260 + 32*132) * 4)

__global__ __launch_bounds__(256) void merge_kernel(
    const float* __restrict__ Hn, const float* __restrict__ src,
    const float* __restrict__ W1, const float* __restrict__ b1,
    const float* __restrict__ W2, const float* __restrict__ b2,
    float* __restrict__ out)
{
    extern __shared__ float sm[];
    float* W_s   = sm;                    // 256 x 128 (W1, then reused for W2)
    float* cat_s = W_s + 256 * 128;       // 32 x 260
    float* hid_s = cat_s + 32 * 260;      // 32 x 132

    const int tid = threadIdx.x;
    const int r0 = blockIdx.x * 32;

    for (int i = tid; i < 256 * 128; i += 256) W_s[i] = W1[i];
    for (int i = tid; i < 32 * 256; i += 256) {
        int r = i >> 8, k = i & 255;
        float v = (k < 128) ? Hn[(size_t)(r0 + r) * 128 + k]
                            : src[(size_t)(r0 + r) * 128 + (k - 128)];
        cat_s[r * 260 + k] = v;
    }
    __syncthreads();

    for (int it = 0; it < 16; it++) {
        int idx = it * 256 + tid;
        int r = idx >> 7, h = idx & 127;
        float acc = b1[h];
#pragma unroll 4
        for (int k = 0; k < 256; k += 4) {
            float4 cv = *(float4*)&cat_s[r * 260 + k];
            acc += cv.x * W_s[(k    ) * 128 + h];
            acc += cv.y * W_s[(k + 1) * 128 + h];
            acc += cv.z * W_s[(k + 2) * 128 + h];
            acc += cv.w * W_s[(k + 3) * 128 + h];
        }
        hid_s[r * 132 + h] = fmaxf(acc, 0.f);
    }
    __syncthreads();

    for (int i = tid; i < 128 * 128; i += 256) W_s[i] = W2[i];
    __syncthreads();

    for (int it = 0; it < 16; it++) {
        int idx = it * 256 + tid;
        int r = idx >> 7, j = idx & 127;
        float acc = b2[j];
#pragma unroll 4
        for (int k = 0; k < 128; k += 4) {
            float4 hv = *(float4*)&hid_s[r * 132 + k];
            acc += hv.x * W_s[(k    ) * 128 + j];
            acc += hv.y * W_s[(k + 1) * 128 + j];
            acc += hv.z * W_s[(k + 2) * 128 + j];
            acc += hv.w * W_s[(k + 3) * 128 + j];
        }
        out[(size_t)(r0 + r) * 128 + j] = acc;
    }
}

// ---------------- launch ----------------
extern "C" void kernel_launch(void* const* d_in, const int* in_sizes, int n_in,
                              void* d_out, int out_size) {
    (void)in_sizes; (void)n_in; (void)out_size;
    const float* src   = (const float*)d_in[0];
    // d_in[1] = src_t (unused by reference)
    const float* seq   = (const float*)d_in[2];
    const float* seq_t = (const float*)d_in[3];
    const float* seq_e = (const float*)d_in[4];
    // d_in[5] = mask (all ones, unused by reference)
    const float* Wi    = (const float*)d_in[6];
    const float* Wh    = (const float*)d_in[7];
    const float* bh    = (const float*)d_in[8];
    const float* W1    = (const float*)d_in[9];
    const float* b1    = (const float*)d_in[10];
    const float* W2    = (const float*)d_in[11];
    const float* b2    = (const float*)d_in[12];
    float* out = (float*)d_out;

    cudaFuncSetAttribute(phase2_lstm, cudaFuncAttributeMaxDynamicSharedMemorySize, P2_SMEM);
    cudaFuncSetAttribute(merge_kernel, cudaFuncAttributeMaxDynamicSharedMemorySize, MG_SMEM);

    float* Hn;
    cudaGetSymbolAddress((void**)&Hn, g_Hn);

    cvt_weights<<<(AA * G4 + 255) / 256, 256>>>(Wi, Wh);
    phase1_gemm<<<dim3(BT / 128, G4 / 128), 256>>>(seq, seq_e, seq_t);
    phase2_lstm<<<BB / 32, 256, P2_SMEM>>>(bh, Hn);
    merge_kernel<<<BB / 32, 256, MG_SMEM>>>(Hn, src, W1, b1, W2, b2, out);
}